// round 1
// baseline (speedup 1.0000x reference)
#include <cuda_runtime.h>
#include <math.h>

// Problem dims
#define BB   4096
#define CINC 64
#define MID  256
#define NOUT 256
#define NC   27
#define KP   576           // packed K: 9 taps * 64 cin (corner uses first 320)
#define EPSV 1e-5f

// GEMM tile config
#define Bb  128
#define Bn  128
#define Bk  16

// ---------------- scratch (__device__ globals; no allocations) ----------------
constexpr size_t SZ_WC = (size_t)NC * MID * KP;     // 3,981,312 floats (~16 MB)
constexpr size_t SZ_PC = (size_t)NC * BB  * KP;     // 63,700,992 floats (~255 MB)
constexpr size_t SZ_H  = (size_t)NC * BB  * MID;    // 28,311,552 floats (~113 MB)

__device__ float g_S   [NC * MID];
__device__ float g_bc  [NC * MID];
__device__ float g_bsum[2 * NOUT];
__device__ float g_Wc  [SZ_WC];
__device__ float g_Pc  [SZ_PC];
__device__ float g_H1  [SZ_H];
__device__ float g_H2  [SZ_H];
__device__ float g_Copy[(size_t)BB * NOUT];

// nonzero tap positions (row-major 5x5 index) per branch family; padded with
// center tap (12) whose weight is forced to 0, so padded products are exactly 0.
__device__ __constant__ int c_pos[3][9] = {
  { 6, 7, 8, 11, 12, 13, 16, 17, 18},   // circle
  { 0, 4, 20, 24, 12, 12, 12, 12, 12},  // corner (5 real taps)
  { 1, 3, 5, 9, 15, 19, 21, 23, 12}     // horse
};
__device__ __constant__ int c_cnt[3] = {9, 5, 9};

// ---------------- helpers ----------------
__device__ __forceinline__ float mish_f(float v) {
  // softplus = max(v,0) + log1p(exp(-|v|))  (matches jax.nn.softplus)
  float sp = fmaxf(v, 0.0f) + log1pf(expf(-fabsf(v)));
  return v * tanhf(sp);
}

// ---------------- packing kernels ----------------
__global__ void pack_bias_kernel(const float* __restrict__ b5,
                                 const float* __restrict__ gamma,
                                 const float* __restrict__ beta,
                                 const float* __restrict__ mean,
                                 const float* __restrict__ var) {
  int i = blockIdx.x * blockDim.x + threadIdx.x;   // < NC*MID
  float s = gamma[i] * rsqrtf(var[i] + EPSV);
  g_S[i]  = s;
  g_bc[i] = (b5[i] - mean[i]) * s + beta[i];
}

__global__ void bias_sums_kernel(const float* __restrict__ b2) {
  int o = threadIdx.x;                              // 256 threads
  float sc = 0.f, sj = 0.f;
  #pragma unroll
  for (int c = 0; c < 9; ++c)  sc += b2[c * NOUT + o];
  #pragma unroll
  for (int c = 9; c < 27; ++c) sj += b2[c * NOUT + o];
  g_bsum[o] = sc;
  g_bsum[NOUT + o] = sj;
}

// Wc[c][m][t*64+cin] = W5[c,m,cin*25+pos] * s   (0 for padded taps)
__global__ void pack_weights_kernel(const float* __restrict__ W5) {
  size_t idx = (size_t)blockIdx.x * 256 + threadIdx.x;   // < NC*MID*KP
  int s   = (int)(idx % KP);
  int t   = s >> 6;
  int cin = s & 63;
  int m   = (int)((idx / KP) % MID);
  int c   = (int)(idx / ((size_t)KP * MID));
  int g   = c / 9;
  float w = 0.f;
  if (t < c_cnt[g]) {
    w = W5[(size_t)(c * MID + m) * 1600 + cin * 25 + c_pos[g][t]] * g_S[c * MID + m];
  }
  g_Wc[idx] = w;
}

// Pc[cp][b][t*64+cin] = x[b, cin, pk+i, pv+j]
__global__ void pack_patches_kernel(const float* __restrict__ x) {
  size_t idx = (size_t)blockIdx.x * 256 + threadIdx.x;   // < NC*BB*KP
  int s   = (int)(idx % KP);
  int t   = s >> 6;
  int cin = s & 63;
  int b   = (int)((idx / KP) % BB);
  int cp  = (int)(idx / ((size_t)KP * BB));
  int g = cp / 9, p = cp % 9;
  int pos = c_pos[g][t];
  int i = pos / 5 + p / 3;
  int j = pos % 5 + p % 3;
  g_Pc[idx] = x[((size_t)(b * CINC + cin) * 7 + i) * 7 + j];
}

// ---------------- shared GEMM core: C[128x128] += A[rows,K] * W[cols,K]^T ----
__device__ __forceinline__ void gemm_block(const float* __restrict__ A, int lda,
                                           const float* __restrict__ W, int ldw,
                                           int K, int brow, int bcol,
                                           float (&acc)[8][8],
                                           float* As, float* Bs) {
  const int tid = threadIdx.x;
  const int tx = tid & 15;
  const int ty = tid >> 4;
  for (int k0 = 0; k0 < K; k0 += Bk) {
    __syncthreads();
    #pragma unroll
    for (int l = 0; l < 2; ++l) {
      int idx = tid + l * 256;
      int row = idx >> 2;          // 0..127
      int kq  = (idx & 3) << 2;    // 0,4,8,12
      float4 va = *reinterpret_cast<const float4*>(A + (size_t)(brow + row) * lda + (k0 + kq));
      As[(kq + 0) * Bb + row] = va.x;
      As[(kq + 1) * Bb + row] = va.y;
      As[(kq + 2) * Bb + row] = va.z;
      As[(kq + 3) * Bb + row] = va.w;
      float4 vw = *reinterpret_cast<const float4*>(W + (size_t)(bcol + row) * ldw + (k0 + kq));
      Bs[(kq + 0) * Bn + row] = vw.x;
      Bs[(kq + 1) * Bn + row] = vw.y;
      Bs[(kq + 2) * Bn + row] = vw.z;
      Bs[(kq + 3) * Bn + row] = vw.w;
    }
    __syncthreads();
    #pragma unroll
    for (int kk = 0; kk < Bk; ++kk) {
      float a[8], bf[8];
      *reinterpret_cast<float4*>(a)      = *reinterpret_cast<const float4*>(As + kk * Bb + ty * 8);
      *reinterpret_cast<float4*>(a + 4)  = *reinterpret_cast<const float4*>(As + kk * Bb + ty * 8 + 4);
      *reinterpret_cast<float4*>(bf)     = *reinterpret_cast<const float4*>(Bs + kk * Bn + tx * 8);
      *reinterpret_cast<float4*>(bf + 4) = *reinterpret_cast<const float4*>(Bs + kk * Bn + tx * 8 + 4);
      #pragma unroll
      for (int i = 0; i < 8; ++i)
        #pragma unroll
        for (int j = 0; j < 8; ++j)
          acc[i][j] = fmaf(a[i], bf[j], acc[i][j]);
    }
  }
}

// ---------------- GEMM1: z = Pc @ Wc^T (+bias') -> mish -> H1 ----------------
__global__ void __launch_bounds__(256) gemm1_kernel() {
  __shared__ float As[Bk * Bb];
  __shared__ float Bs[Bk * Bn];
  int c = blockIdx.z, g = c / 9;
  int brow = blockIdx.y * Bb, bcol = blockIdx.x * Bn;
  int K = c_cnt[g] * 64;       // 576 or 320

  float acc[8][8];
  #pragma unroll
  for (int i = 0; i < 8; ++i)
    #pragma unroll
    for (int j = 0; j < 8; ++j) acc[i][j] = 0.f;

  gemm_block(g_Pc + (size_t)c * BB * KP, KP,
             g_Wc + (size_t)c * MID * KP, KP,
             K, brow, bcol, acc, As, Bs);

  int tx = threadIdx.x & 15, ty = threadIdx.x >> 4;
  int col = bcol + tx * 8;
  float bias[8];
  *reinterpret_cast<float4*>(bias)     = *reinterpret_cast<const float4*>(g_bc + c * MID + col);
  *reinterpret_cast<float4*>(bias + 4) = *reinterpret_cast<const float4*>(g_bc + c * MID + col + 4);
  #pragma unroll
  for (int i = 0; i < 8; ++i) {
    float o[8];
    #pragma unroll
    for (int j = 0; j < 8; ++j) o[j] = mish_f(acc[i][j] + bias[j]);
    size_t off = ((size_t)c * BB + brow + ty * 8 + i) * MID + col;
    *reinterpret_cast<float4*>(g_H1 + off)     = *reinterpret_cast<float4*>(o);
    *reinterpret_cast<float4*>(g_H1 + off + 4) = *reinterpret_cast<float4*>(o + 4);
  }
}

// ---------------- GEMM2: H2 = mish(H1 @ W1^T + b1) ----------------
__global__ void __launch_bounds__(256) gemm2_kernel(const float* __restrict__ W1,
                                                    const float* __restrict__ b1) {
  __shared__ float As[Bk * Bb];
  __shared__ float Bs[Bk * Bn];
  int c = blockIdx.z;
  int brow = blockIdx.y * Bb, bcol = blockIdx.x * Bn;

  float acc[8][8];
  #pragma unroll
  for (int i = 0; i < 8; ++i)
    #pragma unroll
    for (int j = 0; j < 8; ++j) acc[i][j] = 0.f;

  gemm_block(g_H1 + (size_t)c * BB * MID, MID,
             W1 + (size_t)c * MID * MID, MID,
             MID, brow, bcol, acc, As, Bs);

  int tx = threadIdx.x & 15, ty = threadIdx.x >> 4;
  int col = bcol + tx * 8;
  float bias[8];
  *reinterpret_cast<float4*>(bias)     = *reinterpret_cast<const float4*>(b1 + c * MID + col);
  *reinterpret_cast<float4*>(bias + 4) = *reinterpret_cast<const float4*>(b1 + c * MID + col + 4);
  #pragma unroll
  for (int i = 0; i < 8; ++i) {
    float o[8];
    #pragma unroll
    for (int j = 0; j < 8; ++j) o[j] = mish_f(acc[i][j] + bias[j]);
    size_t off = ((size_t)c * BB + brow + ty * 8 + i) * MID + col;
    *reinterpret_cast<float4*>(g_H2 + off)     = *reinterpret_cast<float4*>(o);
    *reinterpret_cast<float4*>(g_H2 + off + 4) = *reinterpret_cast<float4*>(o + 4);
  }
}

// ---------------- GEMM3a: Copy = sum_{c=0..8} H2[c] @ W2[c]^T + bsum_c ------
__global__ void __launch_bounds__(256) gemm3a_kernel(const float* __restrict__ W2) {
  __shared__ float As[Bk * Bb];
  __shared__ float Bs[Bk * Bn];
  int brow = blockIdx.y * Bb, bcol = blockIdx.x * Bn;

  float acc[8][8];
  #pragma unroll
  for (int i = 0; i < 8; ++i)
    #pragma unroll
    for (int j = 0; j < 8; ++j) acc[i][j] = 0.f;

  for (int c = 0; c < 9; ++c) {
    gemm_block(g_H2 + (size_t)c * BB * MID, MID,
               W2 + (size_t)c * NOUT * MID, MID,
               MID, brow, bcol, acc, As, Bs);
  }

  int tx = threadIdx.x & 15, ty = threadIdx.x >> 4;
  int col = bcol + tx * 8;
  float bias[8];
  *reinterpret_cast<float4*>(bias)     = *reinterpret_cast<const float4*>(g_bsum + col);
  *reinterpret_cast<float4*>(bias + 4) = *reinterpret_cast<const float4*>(g_bsum + col + 4);
  #pragma unroll
  for (int i = 0; i < 8; ++i) {
    float o[8];
    #pragma unroll
    for (int j = 0; j < 8; ++j) o[j] = acc[i][j] + bias[j];
    size_t off = (size_t)(brow + ty * 8 + i) * NOUT + col;
    *reinterpret_cast<float4*>(g_Copy + off)     = *reinterpret_cast<float4*>(o);
    *reinterpret_cast<float4*>(g_Copy + off + 4) = *reinterpret_cast<float4*>(o + 4);
  }
}

// ---------------- GEMM3b: out = (sum_{c=9..26} ... + bsum_j) * Copy ---------
__global__ void __launch_bounds__(256) gemm3b_kernel(const float* __restrict__ W2,
                                                     float* __restrict__ out) {
  __shared__ float As[Bk * Bb];
  __shared__ float Bs[Bk * Bn];
  int brow = blockIdx.y * Bb, bcol = blockIdx.x * Bn;

  float acc[8][8];
  #pragma unroll
  for (int i = 0; i < 8; ++i)
    #pragma unroll
    for (int j = 0; j < 8; ++j) acc[i][j] = 0.f;

  for (int c = 9; c < 27; ++c) {
    gemm_block(g_H2 + (size_t)c * BB * MID, MID,
               W2 + (size_t)c * NOUT * MID, MID,
               MID, brow, bcol, acc, As, Bs);
  }

  int tx = threadIdx.x & 15, ty = threadIdx.x >> 4;
  int col = bcol + tx * 8;
  float bias[8];
  *reinterpret_cast<float4*>(bias)     = *reinterpret_cast<const float4*>(g_bsum + NOUT + col);
  *reinterpret_cast<float4*>(bias + 4) = *reinterpret_cast<const float4*>(g_bsum + NOUT + col + 4);
  #pragma unroll
  for (int i = 0; i < 8; ++i) {
    size_t off = (size_t)(brow + ty * 8 + i) * NOUT + col;
    float4 cp0 = *reinterpret_cast<const float4*>(g_Copy + off);
    float4 cp1 = *reinterpret_cast<const float4*>(g_Copy + off + 4);
    float o[8];
    o[0] = (acc[i][0] + bias[0]) * cp0.x;
    o[1] = (acc[i][1] + bias[1]) * cp0.y;
    o[2] = (acc[i][2] + bias[2]) * cp0.z;
    o[3] = (acc[i][3] + bias[3]) * cp0.w;
    o[4] = (acc[i][4] + bias[4]) * cp1.x;
    o[5] = (acc[i][5] + bias[5]) * cp1.y;
    o[6] = (acc[i][6] + bias[6]) * cp1.z;
    o[7] = (acc[i][7] + bias[7]) * cp1.w;
    *reinterpret_cast<float4*>(out + off)     = *reinterpret_cast<float4*>(o);
    *reinterpret_cast<float4*>(out + off + 4) = *reinterpret_cast<float4*>(o + 4);
  }
}

// ---------------- launch ----------------
extern "C" void kernel_launch(void* const* d_in, const int* in_sizes, int n_in,
                              void* d_out, int out_size) {
  const float* x     = (const float*)d_in[0];
  const float* W5    = (const float*)d_in[1];
  const float* b5    = (const float*)d_in[2];
  const float* gamma = (const float*)d_in[3];
  const float* beta  = (const float*)d_in[4];
  const float* mean  = (const float*)d_in[5];
  const float* var   = (const float*)d_in[6];
  const float* W1    = (const float*)d_in[7];
  const float* b1    = (const float*)d_in[8];
  const float* W2    = (const float*)d_in[9];
  const float* b2    = (const float*)d_in[10];
  float* out = (float*)d_out;

  pack_bias_kernel<<<(NC * MID) / 256, 256>>>(b5, gamma, beta, mean, var);
  bias_sums_kernel<<<1, 256>>>(b2);
  pack_weights_kernel<<<(int)(SZ_WC / 256), 256>>>(W5);
  pack_patches_kernel<<<(int)(SZ_PC / 256), 256>>>(x);

  gemm1_kernel<<<dim3(NOUT / Bn, BB / Bb, NC), 256>>>();
  gemm2_kernel<<<dim3(NOUT / Bn, BB / Bb, NC), 256>>>(W1, b1);
  gemm3a_kernel<<<dim3(NOUT / Bn, BB / Bb), 256>>>(W2);
  gemm3b_kernel<<<dim3(NOUT / Bn, BB / Bb), 256>>>(W2, out);
}

// round 4
// speedup vs baseline: 3.1798x; 3.1798x over previous
#include <cuda_runtime.h>
#include <cuda_bf16.h>
#include <stdint.h>
#include <math.h>

// ---------------- problem dims ----------------
#define BB   4096
#define CINC 64
#define MID  256
#define NC   27
#define KP   576
#define EPSV 1e-5f

// ---------------- GEMM tiling ----------------
// CTA tile 128x128, K-chunk 32, 8 warps (2 m x 4 n), warp tile 64x32.
// smem buffers: padded row = 40 bf16 elements (80 B). 4 buffers/stage.
#define ROWB   80          // padded row bytes
#define BUFB   10240       // 128 * 80
#define STAGEB 40960       // 4 buffers
#define SMEM_DYN 81920     // 2 stages

// ---------------- device scratch (no allocations) ----------------
__device__ __nv_bfloat16 g_xt_hi[(size_t)49 * BB * CINC];
__device__ __nv_bfloat16 g_xt_lo[(size_t)49 * BB * CINC];
__device__ __nv_bfloat16 g_Wc_hi[(size_t)NC * MID * KP];
__device__ __nv_bfloat16 g_Wc_lo[(size_t)NC * MID * KP];
__device__ __nv_bfloat16 g_W1_hi[(size_t)NC * MID * MID];
__device__ __nv_bfloat16 g_W1_lo[(size_t)NC * MID * MID];
__device__ __nv_bfloat16 g_W2_hi[(size_t)NC * MID * MID];
__device__ __nv_bfloat16 g_W2_lo[(size_t)NC * MID * MID];
__device__ __nv_bfloat16 g_H1_hi[(size_t)NC * BB * MID];
__device__ __nv_bfloat16 g_H1_lo[(size_t)NC * BB * MID];
__device__ __nv_bfloat16 g_H2_hi[(size_t)NC * BB * MID];
__device__ __nv_bfloat16 g_H2_lo[(size_t)NC * BB * MID];
__device__ float g_P3[(size_t)NC * BB * MID];
__device__ float g_S[NC * MID];
__device__ float g_bc[NC * MID];
__device__ float g_bsum[2 * MID];

__device__ __constant__ int c_pos[3][9] = {
  { 6, 7, 8, 11, 12, 13, 16, 17, 18},   // circle
  { 0, 4, 20, 24, 12, 12, 12, 12, 12},  // corner (5 real taps)
  { 1, 3, 5, 9, 15, 19, 21, 23, 12}     // horse
};
__device__ __constant__ int c_cnt[3] = {9, 5, 9};

// ---------------- helpers ----------------
__device__ __forceinline__ uint32_t smem_u32(const void* p) {
  uint32_t a;
  asm("{ .reg .u64 t; cvta.to.shared.u64 t, %1; cvt.u32.u64 %0, t; }"
      : "=r"(a) : "l"(p));
  return a;
}

__device__ __forceinline__ void cp16(uint32_t dst, const void* src) {
  asm volatile("cp.async.cg.shared.global [%0], [%1], 16;" :: "r"(dst), "l"(src));
}
#define CP_COMMIT() asm volatile("cp.async.commit_group;" ::: "memory")
#define CP_WAIT(n)  asm volatile("cp.async.wait_group %0;" :: "n"(n) : "memory")

__device__ __forceinline__ void mma_bf16(float* d, const uint32_t* a, const uint32_t* b) {
  asm volatile(
    "mma.sync.aligned.m16n8k16.row.col.f32.bf16.bf16.f32 "
    "{%0,%1,%2,%3}, {%4,%5,%6,%7}, {%8,%9}, {%0,%1,%2,%3};"
    : "+f"(d[0]), "+f"(d[1]), "+f"(d[2]), "+f"(d[3])
    : "r"(a[0]), "r"(a[1]), "r"(a[2]), "r"(a[3]), "r"(b[0]), "r"(b[1]));
}

__device__ __forceinline__ float mish_f(float v) {
  float sp = fmaxf(v, 0.0f) + log1pf(expf(-fabsf(v)));
  return v * tanhf(sp);
}

__device__ __forceinline__ void split_bf16(float v, __nv_bfloat16& h, __nv_bfloat16& l) {
  h = __float2bfloat16(v);
  l = __float2bfloat16(v - __bfloat162float(h));
}

// ---------------- packing kernels ----------------
__global__ void pack_bias_kernel(const float* __restrict__ b5,
                                 const float* __restrict__ gamma,
                                 const float* __restrict__ beta,
                                 const float* __restrict__ mean,
                                 const float* __restrict__ var) {
  int i = blockIdx.x * blockDim.x + threadIdx.x;
  float s = gamma[i] * rsqrtf(var[i] + EPSV);
  g_S[i]  = s;
  g_bc[i] = (b5[i] - mean[i]) * s + beta[i];
}

__global__ void bias_sums_kernel(const float* __restrict__ b2) {
  int o = threadIdx.x;
  float sc = 0.f, sj = 0.f;
  #pragma unroll
  for (int c = 0; c < 9; ++c)  sc += b2[c * MID + o];
  #pragma unroll
  for (int c = 9; c < 27; ++c) sj += b2[c * MID + o];
  g_bsum[o] = sc;
  g_bsum[MID + o] = sj;
}

__global__ void pack_wc_kernel(const float* __restrict__ W5) {
  size_t idx = (size_t)blockIdx.x * 256 + threadIdx.x;   // < NC*MID*KP
  int s   = (int)(idx % KP);
  int t   = s >> 6;
  int cin = s & 63;
  int m   = (int)((idx / KP) % MID);
  int c   = (int)(idx / ((size_t)KP * MID));
  int g   = c / 9;
  float w = 0.f;
  if (t < c_cnt[g])
    w = W5[(size_t)(c * MID + m) * 1600 + cin * 25 + c_pos[g][t]] * g_S[c * MID + m];
  __nv_bfloat16 h, l; split_bf16(w, h, l);
  g_Wc_hi[idx] = h;
  g_Wc_lo[idx] = l;
}

__global__ void conv_w_kernel(const float* __restrict__ W1, const float* __restrict__ W2) {
  size_t idx = (size_t)blockIdx.x * 256 + threadIdx.x;   // < 2*NC*MID*MID
  const size_t n1 = (size_t)NC * MID * MID;
  float v; size_t j;
  __nv_bfloat16 *dh, *dl;
  if (idx < n1) { j = idx;      v = W1[j]; dh = g_W1_hi; dl = g_W1_lo; }
  else          { j = idx - n1; v = W2[j]; dh = g_W2_hi; dl = g_W2_lo; }
  __nv_bfloat16 h, l; split_bf16(v, h, l);
  dh[j] = h;
  dl[j] = l;
}

// x[b, cin, i, j] -> x_t[ij][b][cin] (bf16 hi/lo), 2 batches per block
__global__ void pack_xt_kernel(const float* __restrict__ x) {
  __shared__ float sx[2 * 3136];
  int b0 = blockIdx.x * 2;
  for (int i = threadIdx.x; i < 2 * 3136; i += 256)
    sx[i] = x[(size_t)b0 * 3136 + i];
  __syncthreads();
  for (int i = threadIdx.x; i < 2 * 49 * 64; i += 256) {
    int ij = i >> 7;
    int r  = i & 127;
    int bb = r >> 6, cin = r & 63;
    float v = sx[bb * 3136 + cin * 49 + ij];
    __nv_bfloat16 h, l; split_bf16(v, h, l);
    size_t o = (size_t)ij * (BB * CINC) + (size_t)(b0 + bb) * CINC + cin;
    g_xt_hi[o] = h;
    g_xt_lo[o] = l;
  }
}

// ---------------- GEMM building blocks ----------------
// load one 128x32 chunk (A hi/lo and B hi/lo) into a smem stage via cp.async
__device__ __forceinline__ void load_chunk(uint32_t sbase, int stg,
    const __nv_bfloat16* __restrict__ Ahi, const __nv_bfloat16* __restrict__ Alo, int lda,
    const __nv_bfloat16* __restrict__ Bhi, const __nv_bfloat16* __restrict__ Blo, int ldb) {
  uint32_t s = sbase + stg * STAGEB;
  int tid = threadIdx.x;
  #pragma unroll
  for (int i = 0; i < 2; ++i) {
    int idx = tid + i * 256;           // 0..511
    int row = idx >> 2, cq = idx & 3;  // row 0..127, 16B chunk 0..3
    uint32_t so = (uint32_t)(row * ROWB + cq * 16);
    size_t go = (size_t)row * lda + cq * 8;
    size_t gw = (size_t)row * ldb + cq * 8;
    cp16(s + so,            Ahi + go);
    cp16(s + BUFB + so,     Alo + go);
    cp16(s + 2 * BUFB + so, Bhi + gw);
    cp16(s + 3 * BUFB + so, Blo + gw);
  }
  CP_COMMIT();
}

// compute one 32-K chunk: 3-pass bf16 split mma into acc[4][4][4]
__device__ __forceinline__ void compute_chunk(const char* stage, float acc[4][4][4],
                                              int wm, int wn, int lane) {
  const uint16_t* Ah = (const uint16_t*)(stage);
  const uint16_t* Al = (const uint16_t*)(stage + BUFB);
  const uint16_t* Bh = (const uint16_t*)(stage + 2 * BUFB);
  const uint16_t* Bl = (const uint16_t*)(stage + 3 * BUFB);
  int r  = lane >> 2;
  int c2 = (lane & 3) * 2;
  #pragma unroll
  for (int ks = 0; ks < 2; ++ks) {
    int kc = ks * 16 + c2;
    uint32_t ah[4][4], al[4][4];
    #pragma unroll
    for (int mt = 0; mt < 4; ++mt) {
      int row = wm * 64 + mt * 16 + r;
      ah[mt][0] = *(const uint32_t*)(Ah + row * 40 + kc);
      ah[mt][1] = *(const uint32_t*)(Ah + (row + 8) * 40 + kc);
      ah[mt][2] = *(const uint32_t*)(Ah + row * 40 + kc + 8);
      ah[mt][3] = *(const uint32_t*)(Ah + (row + 8) * 40 + kc + 8);
      al[mt][0] = *(const uint32_t*)(Al + row * 40 + kc);
      al[mt][1] = *(const uint32_t*)(Al + (row + 8) * 40 + kc);
      al[mt][2] = *(const uint32_t*)(Al + row * 40 + kc + 8);
      al[mt][3] = *(const uint32_t*)(Al + (row + 8) * 40 + kc + 8);
    }
    #pragma unroll
    for (int nt = 0; nt < 4; ++nt) {
      int nrow = wn * 32 + nt * 8 + r;
      uint32_t bh[2], bl[2];
      bh[0] = *(const uint32_t*)(Bh + nrow * 40 + kc);
      bh[1] = *(const uint32_t*)(Bh + nrow * 40 + kc + 8);
      bl[0] = *(const uint32_t*)(Bl + nrow * 40 + kc);
      bl[1] = *(const uint32_t*)(Bl + nrow * 40 + kc + 8);
      #pragma unroll
      for (int mt = 0; mt < 4; ++mt) {
        mma_bf16(acc[mt][nt], ah[mt], bh);
        mma_bf16(acc[mt][nt], ah[mt], bl);
        mma_bf16(acc[mt][nt], al[mt], bh);
      }
    }
  }
}

// ---------------- GEMM kernels ----------------
__global__ void __launch_bounds__(256, 2) gemm1_mma() {
  extern __shared__ char sm[];
  uint32_t sbase = smem_u32(sm);
  int c = blockIdx.z, brow = blockIdx.y * 128, bcol = blockIdx.x * 128;
  int g = c / 9, p = c % 9, pi = p / 3, pj = p % 3;
  int nk = (g == 1) ? 10 : 18;
  int lane = threadIdx.x & 31, wid = threadIdx.x >> 5;
  int wm = wid & 1, wn = wid >> 1;

  const __nv_bfloat16* Wh = g_Wc_hi + (size_t)c * MID * KP + (size_t)bcol * KP;
  const __nv_bfloat16* Wl = g_Wc_lo + (size_t)c * MID * KP + (size_t)bcol * KP;

  float acc[4][4][4];
  #pragma unroll
  for (int i = 0; i < 4; ++i)
    #pragma unroll
    for (int j = 0; j < 4; ++j)
      #pragma unroll
      for (int q = 0; q < 4; ++q) acc[i][j][q] = 0.f;

  // chunk ch -> tap t = ch>>1, k-offset within tap = (ch&1)*32
  auto aoff = [&](int ch) -> size_t {
    int t = ch >> 1;
    int pos = c_pos[g][t];
    int ij = (pos / 5 + pi) * 7 + (pos % 5 + pj);
    return (size_t)ij * (BB * CINC) + (size_t)brow * CINC + (ch & 1) * 32;
  };

  load_chunk(sbase, 0, g_xt_hi + aoff(0), g_xt_lo + aoff(0), CINC,
             Wh, Wl, KP);
  for (int ch = 0; ch < nk; ++ch) {
    if (ch + 1 < nk) {
      size_t ao = aoff(ch + 1);
      load_chunk(sbase, (ch + 1) & 1, g_xt_hi + ao, g_xt_lo + ao, CINC,
                 Wh + (ch + 1) * 32, Wl + (ch + 1) * 32, KP);
      CP_WAIT(1);
    } else {
      CP_WAIT(0);
    }
    __syncthreads();
    compute_chunk(sm + (ch & 1) * STAGEB, acc, wm, wn, lane);
    __syncthreads();
  }

  // epilogue: mish(acc + bias) -> bf16 hi/lo
  const float* bias = g_bc + c * MID;
  __nv_bfloat16* Hh = g_H1_hi + (size_t)c * BB * MID;
  __nv_bfloat16* Hl = g_H1_lo + (size_t)c * BB * MID;
  int r = lane >> 2, c2 = (lane & 3) * 2;
  #pragma unroll
  for (int mt = 0; mt < 4; ++mt) {
    int row = brow + wm * 64 + mt * 16 + r;
    #pragma unroll
    for (int nt = 0; nt < 4; ++nt) {
      int col = bcol + wn * 32 + nt * 8 + c2;
      float2 bb = *(const float2*)(bias + col);
      float v0 = mish_f(acc[mt][nt][0] + bb.x);
      float v1 = mish_f(acc[mt][nt][1] + bb.y);
      float v2 = mish_f(acc[mt][nt][2] + bb.x);
      float v3 = mish_f(acc[mt][nt][3] + bb.y);
      __nv_bfloat162 h01 = __floats2bfloat162_rn(v0, v1);
      __nv_bfloat162 h23 = __floats2bfloat162_rn(v2, v3);
      __nv_bfloat162 l01 = __floats2bfloat162_rn(v0 - __bfloat162float(__low2bfloat16(h01)),
                                                 v1 - __bfloat162float(__high2bfloat16(h01)));
      __nv_bfloat162 l23 = __floats2bfloat162_rn(v2 - __bfloat162float(__low2bfloat16(h23)),
                                                 v3 - __bfloat162float(__high2bfloat16(h23)));
      *(__nv_bfloat162*)(Hh + (size_t)row * MID + col)       = h01;
      *(__nv_bfloat162*)(Hl + (size_t)row * MID + col)       = l01;
      *(__nv_bfloat162*)(Hh + (size_t)(row + 8) * MID + col) = h23;
      *(__nv_bfloat162*)(Hl + (size_t)(row + 8) * MID + col) = l23;
    }
  }
}

__global__ void __launch_bounds__(256, 2) gemm2_mma(const float* __restrict__ b1) {
  extern __shared__ char sm[];
  uint32_t sbase = smem_u32(sm);
  int c = blockIdx.z, brow = blockIdx.y * 128, bcol = blockIdx.x * 128;
  int lane = threadIdx.x & 31, wid = threadIdx.x >> 5;
  int wm = wid & 1, wn = wid >> 1;

  const __nv_bfloat16* Ahp = g_H1_hi + (size_t)c * BB * MID + (size_t)brow * MID;
  const __nv_bfloat16* Alp = g_H1_lo + (size_t)c * BB * MID + (size_t)brow * MID;
  const __nv_bfloat16* Wh  = g_W1_hi + (size_t)c * MID * MID + (size_t)bcol * MID;
  const __nv_bfloat16* Wl  = g_W1_lo + (size_t)c * MID * MID + (size_t)bcol * MID;

  float acc[4][4][4];
  #pragma unroll
  for (int i = 0; i < 4; ++i)
    #pragma unroll
    for (int j = 0; j < 4; ++j)
      #pragma unroll
      for (int q = 0; q < 4; ++q) acc[i][j][q] = 0.f;

  load_chunk(sbase, 0, Ahp, Alp, MID, Wh, Wl, MID);
  for (int ch = 0; ch < 8; ++ch) {
    if (ch + 1 < 8) {
      load_chunk(sbase, (ch + 1) & 1, Ahp + (ch + 1) * 32, Alp + (ch + 1) * 32, MID,
                 Wh + (ch + 1) * 32, Wl + (ch + 1) * 32, MID);
      CP_WAIT(1);
    } else {
      CP_WAIT(0);
    }
    __syncthreads();
    compute_chunk(sm + (ch & 1) * STAGEB, acc, wm, wn, lane);
    __syncthreads();
  }

  const float* bias = b1 + c * MID;
  __nv_bfloat16* Hh = g_H2_hi + (size_t)c * BB * MID;
  __nv_bfloat16* Hl = g_H2_lo + (size_t)c * BB * MID;
  int r = lane >> 2, c2 = (lane & 3) * 2;
  #pragma unroll
  for (int mt = 0; mt < 4; ++mt) {
    int row = brow + wm * 64 + mt * 16 + r;
    #pragma unroll
    for (int nt = 0; nt < 4; ++nt) {
      int col = bcol + wn * 32 + nt * 8 + c2;
      float2 bb = *(const float2*)(bias + col);
      float v0 = mish_f(acc[mt][nt][0] + bb.x);
      float v1 = mish_f(acc[mt][nt][1] + bb.y);
      float v2 = mish_f(acc[mt][nt][2] + bb.x);
      float v3 = mish_f(acc[mt][nt][3] + bb.y);
      __nv_bfloat162 h01 = __floats2bfloat162_rn(v0, v1);
      __nv_bfloat162 h23 = __floats2bfloat162_rn(v2, v3);
      __nv_bfloat162 l01 = __floats2bfloat162_rn(v0 - __bfloat162float(__low2bfloat16(h01)),
                                                 v1 - __bfloat162float(__high2bfloat16(h01)));
      __nv_bfloat162 l23 = __floats2bfloat162_rn(v2 - __bfloat162float(__low2bfloat16(h23)),
                                                 v3 - __bfloat162float(__high2bfloat16(h23)));
      *(__nv_bfloat162*)(Hh + (size_t)row * MID + col)       = h01;
      *(__nv_bfloat162*)(Hl + (size_t)row * MID + col)       = l01;
      *(__nv_bfloat162*)(Hh + (size_t)(row + 8) * MID + col) = h23;
      *(__nv_bfloat162*)(Hl + (size_t)(row + 8) * MID + col) = l23;
    }
  }
}

__global__ void __launch_bounds__(256, 2) gemm3_mma() {
  extern __shared__ char sm[];
  uint32_t sbase = smem_u32(sm);
  int c = blockIdx.z, brow = blockIdx.y * 128, bcol = blockIdx.x * 128;
  int lane = threadIdx.x & 31, wid = threadIdx.x >> 5;
  int wm = wid & 1, wn = wid >> 1;

  const __nv_bfloat16* Ahp = g_H2_hi + (size_t)c * BB * MID + (size_t)brow * MID;
  const __nv_bfloat16* Alp = g_H2_lo + (size_t)c * BB * MID + (size_t)brow * MID;
  const __nv_bfloat16* Wh  = g_W2_hi + (size_t)c * MID * MID + (size_t)bcol * MID;
  const __nv_bfloat16* Wl  = g_W2_lo + (size_t)c * MID * MID + (size_t)bcol * MID;

  float acc[4][4][4];
  #pragma unroll
  for (int i = 0; i < 4; ++i)
    #pragma unroll
    for (int j = 0; j < 4; ++j)
      #pragma unroll
      for (int q = 0; q < 4; ++q) acc[i][j][q] = 0.f;

  load_chunk(sbase, 0, Ahp, Alp, MID, Wh, Wl, MID);
  for (int ch = 0; ch < 8; ++ch) {
    if (ch + 1 < 8) {
      load_chunk(sbase, (ch + 1) & 1, Ahp + (ch + 1) * 32, Alp + (ch + 1) * 32, MID,
                 Wh + (ch + 1) * 32, Wl + (ch + 1) * 32, MID);
      CP_WAIT(1);
    } else {
      CP_WAIT(0);
    }
    __syncthreads();
    compute_chunk(sm + (ch & 1) * STAGEB, acc, wm, wn, lane);
    __syncthreads();
  }

  float* P = g_P3 + (size_t)c * BB * MID;
  int r = lane >> 2, c2 = (lane & 3) * 2;
  #pragma unroll
  for (int mt = 0; mt < 4; ++mt) {
    int row = brow + wm * 64 + mt * 16 + r;
    #pragma unroll
    for (int nt = 0; nt < 4; ++nt) {
      int col = bcol + wn * 32 + nt * 8 + c2;
      *(float2*)(P + (size_t)row * MID + col)       = make_float2(acc[mt][nt][0], acc[mt][nt][1]);
      *(float2*)(P + (size_t)(row + 8) * MID + col) = make_float2(acc[mt][nt][2], acc[mt][nt][3]);
    }
  }
}

// out = (sum c0..8 + bsC) * (sum c9..26 + bsJ)
__global__ void combine_kernel(float* __restrict__ out) {
  size_t i = (size_t)blockIdx.x * 256 + threadIdx.x;   // < BB*MID
  int o = (int)(i & 255);
  float sc = g_bsum[o], sj = g_bsum[MID + o];
  #pragma unroll
  for (int c = 0; c < 9; ++c)  sc += g_P3[(size_t)c * (BB * MID) + i];
  #pragma unroll
  for (int c = 9; c < 27; ++c) sj += g_P3[(size_t)c * (BB * MID) + i];
  out[i] = sc * sj;
}

// ---------------- launch ----------------
extern "C" void kernel_launch(void* const* d_in, const int* in_sizes, int n_in,
                              void* d_out, int out_size) {
  const float* x     = (const float*)d_in[0];
  const float* W5    = (const float*)d_in[1];
  const float* b5    = (const float*)d_in[2];
  const float* gamma = (const float*)d_in[3];
  const float* beta  = (const float*)d_in[4];
  const float* mean  = (const float*)d_in[5];
  const float* var   = (const float*)d_in[6];
  const float* W1    = (const float*)d_in[7];
  const float* b1    = (const float*)d_in[8];
  const float* W2    = (const float*)d_in[9];
  const float* b2    = (const float*)d_in[10];
  float* out = (float*)d_out;

  cudaFuncSetAttribute(gemm1_mma, cudaFuncAttributeMaxDynamicSharedMemorySize, SMEM_DYN);
  cudaFuncSetAttribute(gemm2_mma, cudaFuncAttributeMaxDynamicSharedMemorySize, SMEM_DYN);
  cudaFuncSetAttribute(gemm3_mma, cudaFuncAttributeMaxDynamicSharedMemorySize, SMEM_DYN);

  pack_bias_kernel<<<NC, 256>>>(b5, gamma, beta, mean, var);
  bias_sums_kernel<<<1, 256>>>(b2);
  pack_wc_kernel<<<(int)(((size_t)NC * MID * KP) / 256), 256>>>(W5);
  conv_w_kernel<<<(int)((2ull * NC * MID * MID) / 256), 256>>>(W1, W2);
  pack_xt_kernel<<<BB / 2, 256>>>(x);

  gemm1_mma<<<dim3(2, BB / 128, NC), 256, SMEM_DYN>>>();
  gemm2_mma<<<dim3(2, BB / 128, NC), 256, SMEM_DYN>>>(b1);
  gemm3_mma<<<dim3(2, BB / 128, NC), 256, SMEM_DYN>>>();
  combine_kernel<<<(BB * MID) / 256, 256>>>(out);
}

// round 5
// speedup vs baseline: 3.3993x; 1.0690x over previous
#include <cuda_runtime.h>
#include <cuda_bf16.h>
#include <stdint.h>
#include <math.h>

// ---------------- problem dims ----------------
#define BB   4096
#define CINC 64
#define MID  256
#define NC   27
#define KP   576
#define EPSV 1e-5f

// ---------------- GEMM tiling ----------------
// CTA tile 128x128, K-chunk 32, 8 warps (2 m x 4 n), warp tile 64x32.
// smem buffers: padded row = 40 bf16 (80 B), 4 buffers/stage, 2 stages.
#define ROWB   80
#define BUFB   10240       // 128 * 80
#define STAGEB 40960       // 4 buffers
#define SMEM_DYN 81920     // 2 stages

// ---------------- device scratch ----------------
__device__ __nv_bfloat16 g_xt_hi[(size_t)49 * BB * CINC];
__device__ __nv_bfloat16 g_xt_lo[(size_t)49 * BB * CINC];
__device__ __nv_bfloat16 g_Wc_hi[(size_t)NC * MID * KP];
__device__ __nv_bfloat16 g_Wc_lo[(size_t)NC * MID * KP];
__device__ __nv_bfloat16 g_W1_hi[(size_t)NC * MID * MID];
__device__ __nv_bfloat16 g_W1_lo[(size_t)NC * MID * MID];
__device__ __nv_bfloat16 g_W2_hi[(size_t)NC * MID * MID];
__device__ __nv_bfloat16 g_W2_lo[(size_t)NC * MID * MID];
__device__ __nv_bfloat16 g_H1_hi[(size_t)NC * BB * MID];
__device__ __nv_bfloat16 g_H1_lo[(size_t)NC * BB * MID];
__device__ __nv_bfloat16 g_H2_hi[(size_t)NC * BB * MID];
__device__ __nv_bfloat16 g_H2_lo[(size_t)NC * BB * MID];
__device__ float g_P3[(size_t)NC * BB * MID];
__device__ float g_bc[NC * MID];
__device__ float g_bsum[2 * MID];

__device__ __constant__ int c_pos[3][9] = {
  { 6, 7, 8, 11, 12, 13, 16, 17, 18},
  { 0, 4, 20, 24, 12, 12, 12, 12, 12},
  { 1, 3, 5, 9, 15, 19, 21, 23, 12}
};
__device__ __constant__ int c_cnt[3] = {9, 5, 9};

// ---------------- helpers ----------------
__device__ __forceinline__ uint32_t smem_u32(const void* p) {
  uint32_t a;
  asm("{ .reg .u64 t; cvta.to.shared.u64 t, %1; cvt.u32.u64 %0, t; }"
      : "=r"(a) : "l"(p));
  return a;
}

__device__ __forceinline__ void cp16(uint32_t dst, const void* src) {
  asm volatile("cp.async.cg.shared.global [%0], [%1], 16;" :: "r"(dst), "l"(src));
}
#define CP_COMMIT() asm volatile("cp.async.commit_group;" ::: "memory")
#define CP_WAIT(n)  asm volatile("cp.async.wait_group %0;" :: "n"(n) : "memory")

__device__ __forceinline__ void ldm4(uint32_t* r, uint32_t addr) {
  asm volatile("ldmatrix.sync.aligned.m8n8.x4.shared.b16 {%0,%1,%2,%3}, [%4];"
               : "=r"(r[0]), "=r"(r[1]), "=r"(r[2]), "=r"(r[3]) : "r"(addr));
}

__device__ __forceinline__ void mma_bf16(float* d, const uint32_t* a, const uint32_t* b) {
  asm volatile(
    "mma.sync.aligned.m16n8k16.row.col.f32.bf16.bf16.f32 "
    "{%0,%1,%2,%3}, {%4,%5,%6,%7}, {%8,%9}, {%0,%1,%2,%3};"
    : "+f"(d[0]), "+f"(d[1]), "+f"(d[2]), "+f"(d[3])
    : "r"(a[0]), "r"(a[1]), "r"(a[2]), "r"(a[3]), "r"(b[0]), "r"(b[1]));
}

__device__ __forceinline__ float mish_f(float v) {
  float sp = fmaxf(v, 0.0f) + log1pf(expf(-fabsf(v)));
  return v * tanhf(sp);
}

__device__ __forceinline__ void split_bf16(float v, __nv_bfloat16& h, __nv_bfloat16& l) {
  h = __float2bfloat16(v);
  l = __float2bfloat16(v - __bfloat162float(h));
}

// ---------------- packing ----------------
// block < 27: g_bc; block 27: g_bsum
__global__ void pack_small(const float* __restrict__ b5, const float* __restrict__ gamma,
                           const float* __restrict__ beta, const float* __restrict__ mean,
                           const float* __restrict__ var, const float* __restrict__ b2) {
  if (blockIdx.x < 27) {
    int i = blockIdx.x * 256 + threadIdx.x;
    float s = gamma[i] * rsqrtf(var[i] + EPSV);
    g_bc[i] = (b5[i] - mean[i]) * s + beta[i];
  } else {
    int o = threadIdx.x;
    float sc = 0.f, sj = 0.f;
    #pragma unroll
    for (int c = 0; c < 9; ++c)  sc += b2[c * MID + o];
    #pragma unroll
    for (int c = 9; c < 27; ++c) sj += b2[c * MID + o];
    g_bsum[o] = sc;
    g_bsum[MID + o] = sj;
  }
}

#define NB_WC ((int)(((size_t)NC * MID * KP) / 256))       // 15552
#define NB_W12 ((int)((2ull * NC * MID * MID) / 256))      // 13824

__global__ void pack_big(const float* __restrict__ W5, const float* __restrict__ W1,
                         const float* __restrict__ W2, const float* __restrict__ gamma,
                         const float* __restrict__ var) {
  int bid = blockIdx.x;
  if (bid < NB_WC) {
    size_t idx = (size_t)bid * 256 + threadIdx.x;
    int s   = (int)(idx % KP);
    int t   = s >> 6;
    int cin = s & 63;
    int m   = (int)((idx / KP) % MID);
    int c   = (int)(idx / ((size_t)KP * MID));
    int g   = c / 9;
    int cm  = c * MID + m;
    float sv = 0.f;
    if ((threadIdx.x & 31) == 0) sv = gamma[cm] * rsqrtf(var[cm] + EPSV);
    sv = __shfl_sync(0xffffffffu, sv, 0);
    float w = 0.f;
    if (t < c_cnt[g])
      w = W5[(size_t)cm * 1600 + cin * 25 + c_pos[g][t]] * sv;
    __nv_bfloat16 h, l; split_bf16(w, h, l);
    g_Wc_hi[idx] = h;
    g_Wc_lo[idx] = l;
  } else {
    size_t idx = (size_t)(bid - NB_WC) * 256 + threadIdx.x;
    const size_t n1 = (size_t)NC * MID * MID;
    float v; size_t j;
    __nv_bfloat16 *dh, *dl;
    if (idx < n1) { j = idx;      v = W1[j]; dh = g_W1_hi; dl = g_W1_lo; }
    else          { j = idx - n1; v = W2[j]; dh = g_W2_hi; dl = g_W2_lo; }
    __nv_bfloat16 h, l; split_bf16(v, h, l);
    dh[j] = h;
    dl[j] = l;
  }
}

// x[b, cin, i, j] -> x_t[ij][b][cin] (bf16 hi/lo)
__global__ void pack_xt_kernel(const float* __restrict__ x) {
  __shared__ float sx[2 * 3136];
  int b0 = blockIdx.x * 2;
  for (int i = threadIdx.x; i < 2 * 3136; i += 256)
    sx[i] = x[(size_t)b0 * 3136 + i];
  __syncthreads();
  for (int i = threadIdx.x; i < 2 * 49 * 64; i += 256) {
    int ij = i >> 7;
    int r  = i & 127;
    int bb = r >> 6, cin = r & 63;
    float v = sx[bb * 3136 + cin * 49 + ij];
    __nv_bfloat16 h, l; split_bf16(v, h, l);
    size_t o = (size_t)ij * (BB * CINC) + (size_t)(b0 + bb) * CINC + cin;
    g_xt_hi[o] = h;
    g_xt_lo[o] = l;
  }
}

// ---------------- GEMM building blocks ----------------
__device__ __forceinline__ void load_chunk(uint32_t sbase, int stg,
    const __nv_bfloat16* __restrict__ Ahi, const __nv_bfloat16* __restrict__ Alo, int lda,
    const __nv_bfloat16* __restrict__ Bhi, const __nv_bfloat16* __restrict__ Blo, int ldb) {
  uint32_t s = sbase + stg * STAGEB;
  int tid = threadIdx.x;
  #pragma unroll
  for (int i = 0; i < 2; ++i) {
    int idx = tid + i * 256;
    int row = idx >> 2, cq = idx & 3;
    uint32_t so = (uint32_t)(row * ROWB + cq * 16);
    size_t go = (size_t)row * lda + cq * 8;
    size_t gw = (size_t)row * ldb + cq * 8;
    cp16(s + so,            Ahi + go);
    cp16(s + BUFB + so,     Alo + go);
    cp16(s + 2 * BUFB + so, Bhi + gw);
    cp16(s + 3 * BUFB + so, Blo + gw);
  }
  CP_COMMIT();
}

// one 32-K chunk via ldmatrix: 12 ldmatrix.x4 + 48 HMMA per warp
// aoffA/aoffB are per-lane byte offsets (precomputed)
__device__ __forceinline__ void compute_chunk(uint32_t ss, float acc[4][4][4],
                                              uint32_t aoffA, uint32_t aoffB) {
  #pragma unroll
  for (int ks = 0; ks < 2; ++ks) {
    uint32_t kb = ks * 32;
    uint32_t ah[4][4], al[4][4], b[8];
    #pragma unroll
    for (int mt = 0; mt < 4; ++mt) {
      ldm4(ah[mt], ss +        aoffA + mt * 1280 + kb);
      ldm4(al[mt], ss + BUFB + aoffA + mt * 1280 + kb);
    }
    ldm4(b,     ss + 2 * BUFB + aoffB + kb);
    ldm4(b + 4, ss + 2 * BUFB + aoffB + 1280 + kb);
    #pragma unroll
    for (int nt = 0; nt < 4; ++nt)
      #pragma unroll
      for (int mt = 0; mt < 4; ++mt) {
        mma_bf16(acc[mt][nt], ah[mt], b + nt * 2);
        mma_bf16(acc[mt][nt], al[mt], b + nt * 2);
      }
    ldm4(b,     ss + 3 * BUFB + aoffB + kb);
    ldm4(b + 4, ss + 3 * BUFB + aoffB + 1280 + kb);
    #pragma unroll
    for (int nt = 0; nt < 4; ++nt)
      #pragma unroll
      for (int mt = 0; mt < 4; ++mt)
        mma_bf16(acc[mt][nt], ah[mt], b + nt * 2);
  }
}

// per-lane ldmatrix source offsets
__device__ __forceinline__ void frag_offsets(int wm, int wn, int lane,
                                             uint32_t& aoffA, uint32_t& aoffB) {
  int t8 = lane >> 3, r8 = lane & 7;
  aoffA = (uint32_t)((wm * 64 + (t8 & 1) * 8 + r8) * ROWB + (t8 >> 1) * 16);
  aoffB = (uint32_t)((wn * 32 + (t8 >> 1) * 8 + r8) * ROWB + (t8 & 1) * 16);
}

// epilogue helpers
__device__ __forceinline__ void epi_mish_store(float acc[4][4][4], const float* __restrict__ bias,
                                               __nv_bfloat16* __restrict__ Hh,
                                               __nv_bfloat16* __restrict__ Hl,
                                               int brow, int bcol, int wm, int wn, int lane) {
  int r = lane >> 2, c2 = (lane & 3) * 2;
  #pragma unroll
  for (int mt = 0; mt < 4; ++mt) {
    int row = brow + wm * 64 + mt * 16 + r;
    #pragma unroll
    for (int nt = 0; nt < 4; ++nt) {
      int col = bcol + wn * 32 + nt * 8 + c2;
      float2 bb = *(const float2*)(bias + col);
      float v0 = mish_f(acc[mt][nt][0] + bb.x);
      float v1 = mish_f(acc[mt][nt][1] + bb.y);
      float v2 = mish_f(acc[mt][nt][2] + bb.x);
      float v3 = mish_f(acc[mt][nt][3] + bb.y);
      __nv_bfloat162 h01 = __floats2bfloat162_rn(v0, v1);
      __nv_bfloat162 h23 = __floats2bfloat162_rn(v2, v3);
      __nv_bfloat162 l01 = __floats2bfloat162_rn(v0 - __bfloat162float(__low2bfloat16(h01)),
                                                 v1 - __bfloat162float(__high2bfloat16(h01)));
      __nv_bfloat162 l23 = __floats2bfloat162_rn(v2 - __bfloat162float(__low2bfloat16(h23)),
                                                 v3 - __bfloat162float(__high2bfloat16(h23)));
      *(__nv_bfloat162*)(Hh + (size_t)row * MID + col)       = h01;
      *(__nv_bfloat162*)(Hl + (size_t)row * MID + col)       = l01;
      *(__nv_bfloat162*)(Hh + (size_t)(row + 8) * MID + col) = h23;
      *(__nv_bfloat162*)(Hl + (size_t)(row + 8) * MID + col) = l23;
    }
  }
}

// ---------------- GEMM kernels ----------------
__global__ void __launch_bounds__(256, 2) gemm1_mma() {
  extern __shared__ char sm[];
  uint32_t sbase = smem_u32(sm);
  int c = blockIdx.z, brow = blockIdx.y * 128, bcol = blockIdx.x * 128;
  int g = c / 9, p = c % 9, pi = p / 3, pj = p % 3;
  int nk = (g == 1) ? 10 : 18;
  int lane = threadIdx.x & 31, wid = threadIdx.x >> 5;
  int wm = wid & 1, wn = wid >> 1;
  uint32_t aoffA, aoffB;
  frag_offsets(wm, wn, lane, aoffA, aoffB);

  const __nv_bfloat16* Wh = g_Wc_hi + (size_t)c * MID * KP + (size_t)bcol * KP;
  const __nv_bfloat16* Wl = g_Wc_lo + (size_t)c * MID * KP + (size_t)bcol * KP;

  float acc[4][4][4];
  #pragma unroll
  for (int i = 0; i < 4; ++i)
    #pragma unroll
    for (int j = 0; j < 4; ++j)
      #pragma unroll
      for (int q = 0; q < 4; ++q) acc[i][j][q] = 0.f;

  auto aoff = [&](int ch) -> size_t {
    int t = ch >> 1;
    int pos = c_pos[g][t];
    int ij = (pos / 5 + pi) * 7 + (pos % 5 + pj);
    return (size_t)ij * (BB * CINC) + (size_t)brow * CINC + (ch & 1) * 32;
  };

  load_chunk(sbase, 0, g_xt_hi + aoff(0), g_xt_lo + aoff(0), CINC, Wh, Wl, KP);
  for (int ch = 0; ch < nk; ++ch) {
    CP_WAIT(0);
    __syncthreads();
    if (ch + 1 < nk) {
      size_t ao = aoff(ch + 1);
      load_chunk(sbase, (ch + 1) & 1, g_xt_hi + ao, g_xt_lo + ao, CINC,
                 Wh + (ch + 1) * 32, Wl + (ch + 1) * 32, KP);
    }
    compute_chunk(sbase + (ch & 1) * STAGEB, acc, aoffA, aoffB);
  }

  epi_mish_store(acc, g_bc + c * MID,
                 g_H1_hi + (size_t)c * BB * MID, g_H1_lo + (size_t)c * BB * MID,
                 brow, bcol, wm, wn, lane);
}

__global__ void __launch_bounds__(256, 2) gemm2_mma(const float* __restrict__ b1) {
  extern __shared__ char sm[];
  uint32_t sbase = smem_u32(sm);
  int c = blockIdx.z, brow = blockIdx.y * 128, bcol = blockIdx.x * 128;
  int lane = threadIdx.x & 31, wid = threadIdx.x >> 5;
  int wm = wid & 1, wn = wid >> 1;
  uint32_t aoffA, aoffB;
  frag_offsets(wm, wn, lane, aoffA, aoffB);

  const __nv_bfloat16* Ahp = g_H1_hi + (size_t)c * BB * MID + (size_t)brow * MID;
  const __nv_bfloat16* Alp = g_H1_lo + (size_t)c * BB * MID + (size_t)brow * MID;
  const __nv_bfloat16* Wh  = g_W1_hi + (size_t)c * MID * MID + (size_t)bcol * MID;
  const __nv_bfloat16* Wl  = g_W1_lo + (size_t)c * MID * MID + (size_t)bcol * MID;

  float acc[4][4][4];
  #pragma unroll
  for (int i = 0; i < 4; ++i)
    #pragma unroll
    for (int j = 0; j < 4; ++j)
      #pragma unroll
      for (int q = 0; q < 4; ++q) acc[i][j][q] = 0.f;

  load_chunk(sbase, 0, Ahp, Alp, MID, Wh, Wl, MID);
  for (int ch = 0; ch < 8; ++ch) {
    CP_WAIT(0);
    __syncthreads();
    if (ch + 1 < 8)
      load_chunk(sbase, (ch + 1) & 1, Ahp + (ch + 1) * 32, Alp + (ch + 1) * 32, MID,
                 Wh + (ch + 1) * 32, Wl + (ch + 1) * 32, MID);
    compute_chunk(sbase + (ch & 1) * STAGEB, acc, aoffA, aoffB);
  }

  epi_mish_store(acc, b1 + c * MID,
                 g_H2_hi + (size_t)c * BB * MID, g_H2_lo + (size_t)c * BB * MID,
                 brow, bcol, wm, wn, lane);
}

__global__ void __launch_bounds__(256, 2) gemm3_mma() {
  extern __shared__ char sm[];
  uint32_t sbase = smem_u32(sm);
  int c = blockIdx.z, brow = blockIdx.y * 128, bcol = blockIdx.x * 128;
  int lane = threadIdx.x & 31, wid = threadIdx.x >> 5;
  int wm = wid & 1, wn = wid >> 1;
  uint32_t aoffA, aoffB;
  frag_offsets(wm, wn, lane, aoffA, aoffB);

  const __nv_bfloat16* Ahp = g_H2_hi + (size_t)c * BB * MID + (size_t)brow * MID;
  const __nv_bfloat16* Alp = g_H2_lo + (size_t)c * BB * MID + (size_t)brow * MID;
  const __nv_bfloat16* Wh  = g_W2_hi + (size_t)c * MID * MID + (size_t)bcol * MID;
  const __nv_bfloat16* Wl  = g_W2_lo + (size_t)c * MID * MID + (size_t)bcol * MID;

  float acc[4][4][4];
  #pragma unroll
  for (int i = 0; i < 4; ++i)
    #pragma unroll
    for (int j = 0; j < 4; ++j)
      #pragma unroll
      for (int q = 0; q < 4; ++q) acc[i][j][q] = 0.f;

  load_chunk(sbase, 0, Ahp, Alp, MID, Wh, Wl, MID);
  for (int ch = 0; ch < 8; ++ch) {
    CP_WAIT(0);
    __syncthreads();
    if (ch + 1 < 8)
      load_chunk(sbase, (ch + 1) & 1, Ahp + (ch + 1) * 32, Alp + (ch + 1) * 32, MID,
                 Wh + (ch + 1) * 32, Wl + (ch + 1) * 32, MID);
    compute_chunk(sbase + (ch & 1) * STAGEB, acc, aoffA, aoffB);
  }

  float* P = g_P3 + (size_t)c * BB * MID;
  int r = lane >> 2, c2 = (lane & 3) * 2;
  #pragma unroll
  for (int mt = 0; mt < 4; ++mt) {
    int row = brow + wm * 64 + mt * 16 + r;
    #pragma unroll
    for (int nt = 0; nt < 4; ++nt) {
      int col = bcol + wn * 32 + nt * 8 + c2;
      *(float2*)(P + (size_t)row * MID + col)       = make_float2(acc[mt][nt][0], acc[mt][nt][1]);
      *(float2*)(P + (size_t)(row + 8) * MID + col) = make_float2(acc[mt][nt][2], acc[mt][nt][3]);
    }
  }
}

// out = (sum c0..8 + bsC) * (sum c9..26 + bsJ), float4 per thread
__global__ void combine_kernel(float* __restrict__ out) {
  size_t i4 = ((size_t)blockIdx.x * 256 + threadIdx.x) * 4;   // < BB*MID
  int o = (int)(i4 & 255);
  float4 sc = *(const float4*)(g_bsum + o);
  float4 sj = *(const float4*)(g_bsum + MID + o);
  #pragma unroll
  for (int c = 0; c < 9; ++c) {
    float4 v = *(const float4*)(g_P3 + (size_t)c * (BB * MID) + i4);
    sc.x += v.x; sc.y += v.y; sc.z += v.z; sc.w += v.w;
  }
  #pragma unroll
  for (int c = 9; c < 27; ++c) {
    float4 v = *(const float4*)(g_P3 + (size_t)c * (BB * MID) + i4);
    sj.x += v.x; sj.y += v.y; sj.z += v.z; sj.w += v.w;
  }
  float4 r = make_float4(sc.x * sj.x, sc.y * sj.y, sc.z * sj.z, sc.w * sj.w);
  *(float4*)(out + i4) = r;
}

// ---------------- launch ----------------
extern "C" void kernel_launch(void* const* d_in, const int* in_sizes, int n_in,
                              void* d_out, int out_size) {
  const float* x     = (const float*)d_in[0];
  const float* W5    = (const float*)d_in[1];
  const float* b5    = (const float*)d_in[2];
  const float* gamma = (const float*)d_in[3];
  const float* beta  = (const float*)d_in[4];
  const float* mean  = (const float*)d_in[5];
  const float* var   = (const float*)d_in[6];
  const float* W1    = (const float*)d_in[7];
  const float* b1    = (const float*)d_in[8];
  const float* W2    = (const float*)d_in[9];
  const float* b2    = (const float*)d_in[10];
  float* out = (float*)d_out;

  cudaFuncSetAttribute(gemm1_mma, cudaFuncAttributeMaxDynamicSharedMemorySize, SMEM_DYN);
  cudaFuncSetAttribute(gemm2_mma, cudaFuncAttributeMaxDynamicSharedMemorySize, SMEM_DYN);
  cudaFuncSetAttribute(gemm3_mma, cudaFuncAttributeMaxDynamicSharedMemorySize, SMEM_DYN);

  pack_small<<<28, 256>>>(b5, gamma, beta, mean, var, b2);
  pack_big<<<NB_WC + NB_W12, 256>>>(W5, W1, W2, gamma, var);
  pack_xt_kernel<<<BB / 2, 256>>>(x);

  gemm1_mma<<<dim3(2, BB / 128, NC), 256, SMEM_DYN>>>();
  gemm2_mma<<<dim3(2, BB / 128, NC), 256, SMEM_DYN>>>(b1);
  gemm3_mma<<<dim3(2, BB / 128, NC), 256, SMEM_DYN>>>();
  combine_kernel<<<(BB * MID) / 1024, 256>>>(out);
}